// round 6
// baseline (speedup 1.0000x reference)
#include <cuda_runtime.h>
#include <math.h>

#define NB    64
#define NC    256
#define HW    4096            // 64*64
#define NPLANES 16384
#define HIDD  16
#define NCOND 32
#define RHID  64
#define ZGRID 592             // 148 SMs x 4

// ---- scratch (no allocations allowed) ----
__device__ float g_semantic[NPLANES];
__device__ int   g_droplist[NPLANES];
__device__ int   g_ndrop;

// ---------------------------------------------------------------------------
__global__ void init_kernel() { g_ndrop = 0; }

// ---------------------------------------------------------------------------
// Pass 1: y = x (streaming copy) + per-plane sums. 8192 blocks x 256 threads,
// 2 planes per block (8 ld.128 + 8 st.128 per thread for deep MLP).
// ---------------------------------------------------------------------------
__global__ void __launch_bounds__(256) copy_reduce_kernel(
    const float* __restrict__ x, float* __restrict__ y)
{
    const int p0 = blockIdx.x * 2;
    const int t  = threadIdx.x;
    const float4* __restrict__ xi =
        reinterpret_cast<const float4*>(x + (size_t)p0 * HW);
    float4* __restrict__ yo =
        reinterpret_cast<float4*>(y + (size_t)p0 * HW);

    float s0 = 0.0f, s1 = 0.0f;
#pragma unroll
    for (int j = 0; j < 4; ++j) {
        float4 v = __ldcs(&xi[t + 256 * j]);
        __stcs(&yo[t + 256 * j], v);
        s0 += (v.x + v.y) + (v.z + v.w);
    }
#pragma unroll
    for (int j = 0; j < 4; ++j) {
        float4 v = __ldcs(&xi[1024 + t + 256 * j]);
        __stcs(&yo[1024 + t + 256 * j], v);
        s1 += (v.x + v.y) + (v.z + v.w);
    }
#pragma unroll
    for (int o = 16; o > 0; o >>= 1) {
        s0 += __shfl_down_sync(0xffffffffu, s0, o);
        s1 += __shfl_down_sync(0xffffffffu, s1, o);
    }

    __shared__ float ws[16];
    if ((t & 31) == 0) { ws[t >> 5] = s0; ws[8 + (t >> 5)] = s1; }
    __syncthreads();
    if (t < 2) {
        const float* w8 = ws + t * 8;
        float tot = ((w8[0] + w8[1]) + (w8[2] + w8[3]))
                  + ((w8[4] + w8[5]) + (w8[6] + w8[7]));
        g_semantic[p0 + t] = tot * (1.0f / 4096.0f);
    }
}

// ---------------------------------------------------------------------------
// Pass 2: per-batch tiny MLPs + top-k mask + dropped-plane compaction.
// 64 blocks x 256 threads.
// ---------------------------------------------------------------------------
__global__ void select_kernel(
    const float* __restrict__ base_cr,
    const float* __restrict__ embed,     // [3,16]
    const float* __restrict__ snr_w1,    // [16,1]
    const float* __restrict__ snr_b1,    // [16]
    const float* __restrict__ snr_w2,    // [16,16]
    const float* __restrict__ snr_b2,    // [16]
    const float* __restrict__ sem_w,     // [16,256]
    const float* __restrict__ cond_w,    // [16,32]
    const float* __restrict__ out_w,     // [256,16]
    const float* __restrict__ r_w1,      // [64,288]
    const float* __restrict__ r_b1,      // [64]
    const float* __restrict__ r_w2,      // [64,64]
    const float* __restrict__ r_b2,      // [64]
    const float* __restrict__ r_w3,      // [1,64]
    const float* __restrict__ r_b3,      // [1]
    const int*   __restrict__ channel_idx,
    const int*   __restrict__ snr_db,
    float* __restrict__ out_cr)
{
    const int b = blockIdx.x;
    const int t = threadIdx.x;

    __shared__ float sem[NC];
    __shared__ float cond[NCOND];
    __shared__ float fused[HIDD];
    __shared__ float w[NC];
    __shared__ float r1[RHID];
    __shared__ float r2[RHID];
    __shared__ int   k_sh;

    sem[t] = g_semantic[b * NC + t];

    if (t < HIDD) {
        cond[t] = embed[channel_idx[0] * 16 + t];
    }
    if (t >= 32 && t < 48) {
        const int i = t - 32;
        const float snr_norm = (float)snr_db[0] / 28.0f;
        float acc = snr_b2[i];
#pragma unroll
        for (int j = 0; j < 16; ++j) {
            float hj = fmaxf(snr_norm * snr_w1[j] + snr_b1[j], 0.0f);
            acc += hj * snr_w2[i * 16 + j];
        }
        cond[16 + i] = fmaxf(acc, 0.0f);
    }
    __syncthreads();

    // fused = relu(sem @ sem_w.T + cond @ cond_w.T)  [16]
    if (t < HIDD) {
        float acc = 0.0f;
        for (int c = 0; c < NC; ++c)    acc += sem[c]  * sem_w[t * NC + c];
        for (int j = 0; j < NCOND; ++j) acc += cond[j] * cond_w[t * NCOND + j];
        fused[t] = fmaxf(acc, 0.0f);
    }

    // rate controller layer 1
    if (t < RHID) {
        float acc = r_b1[t];
        const float* __restrict__ wr = r_w1 + t * (NC + NCOND);
        for (int j = 0; j < NC; ++j)    acc += sem[j]  * wr[j];
        for (int j = 0; j < NCOND; ++j) acc += cond[j] * wr[NC + j];
        r1[t] = fmaxf(acc, 0.0f);
    }
    __syncthreads();

    // weights = sigmoid(fused @ out_w.T)  [256]
    {
        float acc = 0.0f;
#pragma unroll
        for (int h = 0; h < HIDD; ++h) acc += fused[h] * out_w[t * HIDD + h];
        w[t] = 1.0f / (1.0f + expf(-acc));
    }

    // rate controller layer 2
    if (t < RHID) {
        float acc = r_b2[t];
#pragma unroll
        for (int j = 0; j < RHID; ++j) acc += r1[j] * r_w2[t * RHID + j];
        r2[t] = fmaxf(acc, 0.0f);
    }
    __syncthreads();

    if (t == 0) {
        float acc = r_b3[0];
#pragma unroll
        for (int j = 0; j < RHID; ++j) acc += r2[j] * r_w3[j];
        float raw = 1.0f / (1.0f + expf(-acc));
        float dyn = 0.3f + 0.7f * raw;
        float cr  = 0.3f * base_cr[0] + 0.7f * dyn;
        cr = fminf(fmaxf(cr, 0.3f), 1.0f);
        out_cr[b] = cr;
        float crs = fminf(fmaxf(cr, 0.001f), 1.0f);
        int kk = (int)rintf(crs * 256.0f);   // round-half-even == jnp.round
        kk = min(max(kk, 1), 256);
        k_sh = kk;
    }
    __syncthreads();

    // stable descending rank; dropped channels pushed to compact list
    const float wc = w[t];
    int rank = 0;
    for (int j = 0; j < NC; ++j) {
        float wj = w[j];
        rank += (wj > wc) || (wj == wc && j < t);
    }
    if (rank >= k_sh) {
        int i = atomicAdd(&g_ndrop, 1);
        g_droplist[i] = b * NC + t;
    }
}

// ---------------------------------------------------------------------------
// Pass 3: zero out dropped planes from the compact list. 592 blocks,
// grid-stride; every block does real store work -> uniform stream.
// ---------------------------------------------------------------------------
__global__ void __launch_bounds__(256) zero_kernel(float* __restrict__ y) {
    const int n = g_ndrop;
    const int t = threadIdx.x;
    const float4 z = make_float4(0.0f, 0.0f, 0.0f, 0.0f);
    for (int i = blockIdx.x; i < n; i += ZGRID) {
        const int pl = g_droplist[i];
        float4* __restrict__ yo =
            reinterpret_cast<float4*>(y + (size_t)pl * HW);
#pragma unroll
        for (int j = 0; j < 4; ++j)
            __stcs(&yo[t + 256 * j], z);
    }
}

// ---------------------------------------------------------------------------
extern "C" void kernel_launch(void* const* d_in, const int* in_sizes, int n_in,
                              void* d_out, int out_size) {
    const float* x       = (const float*)d_in[0];
    const float* base_cr = (const float*)d_in[1];
    const float* embed   = (const float*)d_in[2];
    const float* snr_w1  = (const float*)d_in[3];
    const float* snr_b1  = (const float*)d_in[4];
    const float* snr_w2  = (const float*)d_in[5];
    const float* snr_b2  = (const float*)d_in[6];
    const float* sem_w   = (const float*)d_in[7];
    const float* cond_w  = (const float*)d_in[8];
    const float* out_w   = (const float*)d_in[9];
    const float* r_w1    = (const float*)d_in[10];
    const float* r_b1    = (const float*)d_in[11];
    const float* r_w2    = (const float*)d_in[12];
    const float* r_b2    = (const float*)d_in[13];
    const float* r_w3    = (const float*)d_in[14];
    const float* r_b3    = (const float*)d_in[15];
    const int*   ch_idx  = (const int*)d_in[16];
    const int*   snr_db  = (const int*)d_in[17];

    float* y      = (float*)d_out;
    float* out_cr = y + (size_t)NPLANES * HW;   // cr_values appended after y

    init_kernel<<<1, 1>>>();
    copy_reduce_kernel<<<NPLANES / 2, 256>>>(x, y);
    select_kernel<<<NB, 256>>>(base_cr, embed, snr_w1, snr_b1, snr_w2, snr_b2,
                               sem_w, cond_w, out_w,
                               r_w1, r_b1, r_w2, r_b2, r_w3, r_b3,
                               ch_idx, snr_db, out_cr);
    zero_kernel<<<ZGRID, 256>>>(y);
}

// round 7
// speedup vs baseline: 1.0128x; 1.0128x over previous
#include <cuda_runtime.h>
#include <math.h>

#define NB    64
#define NC    256
#define HW    4096            // 64*64
#define NPLANES 16384
#define HIDD  16
#define NCOND 32
#define RHID  64
#define ZGRID 1184            // 148 SMs x 8
#define CHUNK 8               // droplist entries prefetched per block iter

// ---- scratch (no allocations allowed) ----
__device__ float g_semantic[NPLANES];
__device__ int   g_droplist[NPLANES];
__device__ int   g_ndrop;

// ---------------------------------------------------------------------------
// Pass 1: y = x (streaming copy) + per-plane sum. 16384 blocks x 256 threads.
// Block 0 also resets g_ndrop (consumed only after this kernel completes).
// ---------------------------------------------------------------------------
__global__ void __launch_bounds__(256) copy_reduce_kernel(
    const float* __restrict__ x, float* __restrict__ y)
{
    const int bc = blockIdx.x;
    const int t  = threadIdx.x;
    if (bc == 0 && t == 0) g_ndrop = 0;

    const float4* __restrict__ xi =
        reinterpret_cast<const float4*>(x + (size_t)bc * HW);
    float4* __restrict__ yo =
        reinterpret_cast<float4*>(y + (size_t)bc * HW);

    float s = 0.0f;
#pragma unroll
    for (int j = 0; j < 4; ++j) {
        float4 v = __ldcs(&xi[t + 256 * j]);
        __stcs(&yo[t + 256 * j], v);
        s += (v.x + v.y) + (v.z + v.w);
    }
#pragma unroll
    for (int o = 16; o > 0; o >>= 1)
        s += __shfl_down_sync(0xffffffffu, s, o);

    __shared__ float ws[8];
    if ((t & 31) == 0) ws[t >> 5] = s;
    __syncthreads();
    if (t == 0) {
        float tot = ((ws[0] + ws[1]) + (ws[2] + ws[3]))
                  + ((ws[4] + ws[5]) + (ws[6] + ws[7]));
        g_semantic[bc] = tot * (1.0f / 4096.0f);
    }
}

// ---------------------------------------------------------------------------
// Pass 2: per-batch tiny MLPs + top-k mask + dropped-plane compaction.
// 64 blocks x 256 threads.
// ---------------------------------------------------------------------------
__global__ void select_kernel(
    const float* __restrict__ base_cr,
    const float* __restrict__ embed,     // [3,16]
    const float* __restrict__ snr_w1,    // [16,1]
    const float* __restrict__ snr_b1,    // [16]
    const float* __restrict__ snr_w2,    // [16,16]
    const float* __restrict__ snr_b2,    // [16]
    const float* __restrict__ sem_w,     // [16,256]
    const float* __restrict__ cond_w,    // [16,32]
    const float* __restrict__ out_w,     // [256,16]
    const float* __restrict__ r_w1,      // [64,288]
    const float* __restrict__ r_b1,      // [64]
    const float* __restrict__ r_w2,      // [64,64]
    const float* __restrict__ r_b2,      // [64]
    const float* __restrict__ r_w3,      // [1,64]
    const float* __restrict__ r_b3,      // [1]
    const int*   __restrict__ channel_idx,
    const int*   __restrict__ snr_db,
    float* __restrict__ out_cr)
{
    const int b = blockIdx.x;
    const int t = threadIdx.x;

    __shared__ float sem[NC];
    __shared__ float cond[NCOND];
    __shared__ float fused[HIDD];
    __shared__ float w[NC];
    __shared__ float r1[RHID];
    __shared__ float r2[RHID];
    __shared__ int   k_sh;

    sem[t] = g_semantic[b * NC + t];

    if (t < HIDD) {
        cond[t] = embed[channel_idx[0] * 16 + t];
    }
    if (t >= 32 && t < 48) {
        const int i = t - 32;
        const float snr_norm = (float)snr_db[0] / 28.0f;
        float acc = snr_b2[i];
#pragma unroll
        for (int j = 0; j < 16; ++j) {
            float hj = fmaxf(snr_norm * snr_w1[j] + snr_b1[j], 0.0f);
            acc += hj * snr_w2[i * 16 + j];
        }
        cond[16 + i] = fmaxf(acc, 0.0f);
    }
    __syncthreads();

    // fused = relu(sem @ sem_w.T + cond @ cond_w.T)  [16]
    if (t < HIDD) {
        float acc = 0.0f;
        for (int c = 0; c < NC; ++c)    acc += sem[c]  * sem_w[t * NC + c];
        for (int j = 0; j < NCOND; ++j) acc += cond[j] * cond_w[t * NCOND + j];
        fused[t] = fmaxf(acc, 0.0f);
    }

    // rate controller layer 1
    if (t < RHID) {
        float acc = r_b1[t];
        const float* __restrict__ wr = r_w1 + t * (NC + NCOND);
        for (int j = 0; j < NC; ++j)    acc += sem[j]  * wr[j];
        for (int j = 0; j < NCOND; ++j) acc += cond[j] * wr[NC + j];
        r1[t] = fmaxf(acc, 0.0f);
    }
    __syncthreads();

    // weights = sigmoid(fused @ out_w.T)  [256]
    {
        float acc = 0.0f;
#pragma unroll
        for (int h = 0; h < HIDD; ++h) acc += fused[h] * out_w[t * HIDD + h];
        w[t] = 1.0f / (1.0f + expf(-acc));
    }

    // rate controller layer 2
    if (t < RHID) {
        float acc = r_b2[t];
#pragma unroll
        for (int j = 0; j < RHID; ++j) acc += r1[j] * r_w2[t * RHID + j];
        r2[t] = fmaxf(acc, 0.0f);
    }
    __syncthreads();

    if (t == 0) {
        float acc = r_b3[0];
#pragma unroll
        for (int j = 0; j < RHID; ++j) acc += r2[j] * r_w3[j];
        float raw = 1.0f / (1.0f + expf(-acc));
        float dyn = 0.3f + 0.7f * raw;
        float cr  = 0.3f * base_cr[0] + 0.7f * dyn;
        cr = fminf(fmaxf(cr, 0.3f), 1.0f);
        out_cr[b] = cr;
        float crs = fminf(fmaxf(cr, 0.001f), 1.0f);
        int kk = (int)rintf(crs * 256.0f);   // round-half-even == jnp.round
        kk = min(max(kk, 1), 256);
        k_sh = kk;
    }
    __syncthreads();

    // stable descending rank; dropped channels pushed to compact list
    const float wc = w[t];
    int rank = 0;
    for (int j = 0; j < NC; ++j) {
        float wj = w[j];
        rank += (wj > wc) || (wj == wc && j < t);
    }
    if (rank >= k_sh) {
        int i = atomicAdd(&g_ndrop, 1);
        g_droplist[i] = b * NC + t;
    }
}

// ---------------------------------------------------------------------------
// Pass 3: zero dropped planes. 1184 blocks; each outer iter prefetches CHUNK
// droplist indices in one round-trip, then streams 4 STG.128/thread per plane
// with no dependent loads in between.
// ---------------------------------------------------------------------------
__global__ void __launch_bounds__(256) zero_kernel(float* __restrict__ y) {
    const int n = g_ndrop;
    const int t = threadIdx.x;
    __shared__ int idxs[CHUNK];
    const float4 z = make_float4(0.0f, 0.0f, 0.0f, 0.0f);

    for (int base = blockIdx.x * CHUNK; base < n; base += ZGRID * CHUNK) {
        const int m = min(CHUNK, n - base);
        if (t < m) idxs[t] = g_droplist[base + t];
        __syncthreads();
        for (int i = 0; i < m; ++i) {
            float4* __restrict__ yo =
                reinterpret_cast<float4*>(y + (size_t)idxs[i] * HW);
#pragma unroll
            for (int j = 0; j < 4; ++j)
                __stcs(&yo[t + 256 * j], z);
        }
        __syncthreads();
    }
}

// ---------------------------------------------------------------------------
extern "C" void kernel_launch(void* const* d_in, const int* in_sizes, int n_in,
                              void* d_out, int out_size) {
    const float* x       = (const float*)d_in[0];
    const float* base_cr = (const float*)d_in[1];
    const float* embed   = (const float*)d_in[2];
    const float* snr_w1  = (const float*)d_in[3];
    const float* snr_b1  = (const float*)d_in[4];
    const float* snr_w2  = (const float*)d_in[5];
    const float* snr_b2  = (const float*)d_in[6];
    const float* sem_w   = (const float*)d_in[7];
    const float* cond_w  = (const float*)d_in[8];
    const float* out_w   = (const float*)d_in[9];
    const float* r_w1    = (const float*)d_in[10];
    const float* r_b1    = (const float*)d_in[11];
    const float* r_w2    = (const float*)d_in[12];
    const float* r_b2    = (const float*)d_in[13];
    const float* r_w3    = (const float*)d_in[14];
    const float* r_b3    = (const float*)d_in[15];
    const int*   ch_idx  = (const int*)d_in[16];
    const int*   snr_db  = (const int*)d_in[17];

    float* y      = (float*)d_out;
    float* out_cr = y + (size_t)NPLANES * HW;   // cr_values appended after y

    copy_reduce_kernel<<<NPLANES, 256>>>(x, y);
    select_kernel<<<NB, 256>>>(base_cr, embed, snr_w1, snr_b1, snr_w2, snr_b2,
                               sem_w, cond_w, out_w,
                               r_w1, r_b1, r_w2, r_b2, r_w3, r_b3,
                               ch_idx, snr_db, out_cr);
    zero_kernel<<<ZGRID, 256>>>(y);
}

// round 8
// speedup vs baseline: 1.1578x; 1.1431x over previous
#include <cuda_runtime.h>
#include <math.h>

#define NB    64
#define NC    256
#define HW    4096            // 64*64
#define NPLANES 16384
#define HIDD  16
#define NCOND 32
#define RHID  64
#define ZGRID 1184            // 148 SMs x 8
#define CHUNK 8               // droplist entries prefetched per block iter

// ---- scratch (no allocations allowed) ----
__device__ float g_semantic[NPLANES];
__device__ int   g_droplist[NPLANES];
__device__ int   g_ndrop;

// ---------------------------------------------------------------------------
// Pass 1: y = x (streaming copy) + per-plane sum. 16384 blocks x 256 threads.
// Block 0 also resets g_ndrop (consumed only after this kernel completes).
// ---------------------------------------------------------------------------
__global__ void __launch_bounds__(256) copy_reduce_kernel(
    const float* __restrict__ x, float* __restrict__ y)
{
    const int bc = blockIdx.x;
    const int t  = threadIdx.x;
    if (bc == 0 && t == 0) g_ndrop = 0;

    const float4* __restrict__ xi =
        reinterpret_cast<const float4*>(x + (size_t)bc * HW);
    float4* __restrict__ yo =
        reinterpret_cast<float4*>(y + (size_t)bc * HW);

    float s = 0.0f;
#pragma unroll
    for (int j = 0; j < 4; ++j) {
        float4 v = __ldcs(&xi[t + 256 * j]);
        __stcs(&yo[t + 256 * j], v);
        s += (v.x + v.y) + (v.z + v.w);
    }
#pragma unroll
    for (int o = 16; o > 0; o >>= 1)
        s += __shfl_down_sync(0xffffffffu, s, o);

    __shared__ float ws[8];
    if ((t & 31) == 0) ws[t >> 5] = s;
    __syncthreads();
    if (t == 0) {
        float tot = ((ws[0] + ws[1]) + (ws[2] + ws[3]))
                  + ((ws[4] + ws[5]) + (ws[6] + ws[7]));
        g_semantic[bc] = tot * (1.0f / 4096.0f);
    }
}

// ---------------------------------------------------------------------------
__device__ __forceinline__ float warp_sum(float v) {
#pragma unroll
    for (int o = 16; o > 0; o >>= 1)
        v += __shfl_down_sync(0xffffffffu, v, o);
    return v;
}

// ---------------------------------------------------------------------------
// Pass 2: per-batch tiny MLPs + top-k mask + dropped-plane compaction.
// 64 blocks x 256 threads. All dot products are WARP-parallel: lanes read
// consecutive weights (coalesced), then shfl-reduce.
// ---------------------------------------------------------------------------
__global__ void __launch_bounds__(256) select_kernel(
    const float* __restrict__ base_cr,
    const float* __restrict__ embed,     // [3,16]
    const float* __restrict__ snr_w1,    // [16,1]
    const float* __restrict__ snr_b1,    // [16]
    const float* __restrict__ snr_w2,    // [16,16]
    const float* __restrict__ snr_b2,    // [16]
    const float* __restrict__ sem_w,     // [16,256]
    const float* __restrict__ cond_w,    // [16,32]
    const float* __restrict__ out_w,     // [256,16]
    const float* __restrict__ r_w1,      // [64,288]
    const float* __restrict__ r_b1,      // [64]
    const float* __restrict__ r_w2,      // [64,64]
    const float* __restrict__ r_b2,      // [64]
    const float* __restrict__ r_w3,      // [1,64]
    const float* __restrict__ r_b3,      // [1]
    const int*   __restrict__ channel_idx,
    const int*   __restrict__ snr_db,
    float* __restrict__ out_cr)
{
    const int b    = blockIdx.x;
    const int t    = threadIdx.x;
    const int warp = t >> 5;
    const int lane = t & 31;

    __shared__ float sem[NC];
    __shared__ float cond[NCOND];
    __shared__ float fused[HIDD];
    __shared__ float w[NC];
    __shared__ float r1[RHID];
    __shared__ float r2[RHID];
    __shared__ int   k_sh;

    sem[t] = g_semantic[b * NC + t];

    if (t < HIDD) {
        cond[t] = embed[channel_idx[0] * 16 + t];
    } else if (t < 2 * HIDD) {
        const int i = t - HIDD;
        const float snr_norm = (float)snr_db[0] / 28.0f;
        float acc = snr_b2[i];
#pragma unroll
        for (int j = 0; j < 16; ++j) {
            float hj = fmaxf(snr_norm * snr_w1[j] + snr_b1[j], 0.0f);
            acc += hj * snr_w2[i * 16 + j];
        }
        cond[16 + i] = fmaxf(acc, 0.0f);
    }
    __syncthreads();

    // ---- phase A: fused[16] (2 per warp) + r1[64] (8 per warp) ----
#pragma unroll
    for (int q = 0; q < 2; ++q) {
        const int o = warp * 2 + q;
        float acc = 0.0f;
#pragma unroll
        for (int j = lane; j < NC; j += 32) acc += sem[j] * sem_w[o * NC + j];
        acc += cond[lane] * cond_w[o * NCOND + lane];
        acc = warp_sum(acc);
        if (lane == 0) fused[o] = fmaxf(acc, 0.0f);
    }
#pragma unroll
    for (int q = 0; q < 8; ++q) {
        const int o = warp * 8 + q;
        const float* __restrict__ wr = r_w1 + o * (NC + NCOND);
        float acc = 0.0f;
#pragma unroll
        for (int j = lane; j < NC; j += 32) acc += sem[j] * wr[j];
        acc += cond[lane] * wr[NC + lane];
        acc = warp_sum(acc);
        if (lane == 0) r1[o] = fmaxf(acc + r_b1[o], 0.0f);
    }
    __syncthreads();

    // ---- phase B: weights[256] (1 per thread, float4 rows) + r2[64] ----
    {
        const float4* __restrict__ ow =
            reinterpret_cast<const float4*>(out_w + t * HIDD);
        float acc = 0.0f;
#pragma unroll
        for (int q = 0; q < 4; ++q) {
            float4 v = ow[q];
            acc += v.x * fused[q * 4 + 0] + v.y * fused[q * 4 + 1]
                 + v.z * fused[q * 4 + 2] + v.w * fused[q * 4 + 3];
        }
        w[t] = 1.0f / (1.0f + expf(-acc));
    }
#pragma unroll
    for (int q = 0; q < 8; ++q) {
        const int o = warp * 8 + q;
        float acc = r1[lane]      * r_w2[o * RHID + lane]
                  + r1[lane + 32] * r_w2[o * RHID + lane + 32];
        acc = warp_sum(acc);
        if (lane == 0) r2[o] = fmaxf(acc + r_b2[o], 0.0f);
    }
    __syncthreads();

    // ---- phase C: r3 scalar + cr + k (warp 0) ----
    if (warp == 0) {
        float acc = r2[lane]      * r_w3[lane]
                  + r2[lane + 32] * r_w3[lane + 32];
        acc = warp_sum(acc);
        if (lane == 0) {
            acc += r_b3[0];
            float raw = 1.0f / (1.0f + expf(-acc));
            float dyn = 0.3f + 0.7f * raw;
            float cr  = 0.3f * base_cr[0] + 0.7f * dyn;
            cr = fminf(fmaxf(cr, 0.3f), 1.0f);
            out_cr[b] = cr;
            float crs = fminf(fmaxf(cr, 0.001f), 1.0f);
            int kk = (int)rintf(crs * 256.0f);   // round-half-even == jnp.round
            kk = min(max(kk, 1), 256);
            k_sh = kk;
        }
    }
    __syncthreads();

    // ---- stable descending rank; dropped channels -> compact list ----
    const float wc = w[t];
    int rank = 0;
    for (int j = 0; j < NC; ++j) {
        float wj = w[j];
        rank += (wj > wc) || (wj == wc && j < t);
    }
    if (rank >= k_sh) {
        int i = atomicAdd(&g_ndrop, 1);
        g_droplist[i] = b * NC + t;
    }
}

// ---------------------------------------------------------------------------
// Pass 3: zero dropped planes. 1184 blocks; each outer iter prefetches CHUNK
// droplist indices in one round-trip, then streams stores with no dependent
// loads in between.
// ---------------------------------------------------------------------------
__global__ void __launch_bounds__(256) zero_kernel(float* __restrict__ y) {
    const int n = g_ndrop;
    const int t = threadIdx.x;
    __shared__ int idxs[CHUNK];
    const float4 z = make_float4(0.0f, 0.0f, 0.0f, 0.0f);

    for (int base = blockIdx.x * CHUNK; base < n; base += ZGRID * CHUNK) {
        const int m = min(CHUNK, n - base);
        if (t < m) idxs[t] = g_droplist[base + t];
        __syncthreads();
        for (int i = 0; i < m; ++i) {
            float4* __restrict__ yo =
                reinterpret_cast<float4*>(y + (size_t)idxs[i] * HW);
#pragma unroll
            for (int j = 0; j < 4; ++j)
                __stcs(&yo[t + 256 * j], z);
        }
        __syncthreads();
    }
}

// ---------------------------------------------------------------------------
extern "C" void kernel_launch(void* const* d_in, const int* in_sizes, int n_in,
                              void* d_out, int out_size) {
    const float* x       = (const float*)d_in[0];
    const float* base_cr = (const float*)d_in[1];
    const float* embed   = (const float*)d_in[2];
    const float* snr_w1  = (const float*)d_in[3];
    const float* snr_b1  = (const float*)d_in[4];
    const float* snr_w2  = (const float*)d_in[5];
    const float* snr_b2  = (const float*)d_in[6];
    const float* sem_w   = (const float*)d_in[7];
    const float* cond_w  = (const float*)d_in[8];
    const float* out_w   = (const float*)d_in[9];
    const float* r_w1    = (const float*)d_in[10];
    const float* r_b1    = (const float*)d_in[11];
    const float* r_w2    = (const float*)d_in[12];
    const float* r_b2    = (const float*)d_in[13];
    const float* r_w3    = (const float*)d_in[14];
    const float* r_b3    = (const float*)d_in[15];
    const int*   ch_idx  = (const int*)d_in[16];
    const int*   snr_db  = (const int*)d_in[17];

    float* y      = (float*)d_out;
    float* out_cr = y + (size_t)NPLANES * HW;   // cr_values appended after y

    copy_reduce_kernel<<<NPLANES, 256>>>(x, y);
    select_kernel<<<NB, 256>>>(base_cr, embed, snr_w1, snr_b1, snr_w2, snr_b2,
                               sem_w, cond_w, out_w,
                               r_w1, r_b1, r_w2, r_b2, r_w3, r_b3,
                               ch_idx, snr_db, out_cr);
    zero_kernel<<<ZGRID, 256>>>(y);
}